// round 2
// baseline (speedup 1.0000x reference)
#include <cuda_runtime.h>
#include <cstdint>
#include <math.h>

#define NUM_LEVELS 16
#define TABLE_SIZE (1u << 20)
#define TMASK (TABLE_SIZE - 1u)
#define P2 2654435761u
#define P3 805459861u

struct ResParams {
    int res[NUM_LEVELS];
};

__global__ __launch_bounds__(256)
void hash_encoder_kernel(const float* __restrict__ pos,
                         const float* __restrict__ tables,
                         float* __restrict__ out,
                         int n_points,
                         ResParams rp)
{
    long long tid = (long long)blockIdx.x * blockDim.x + threadIdx.x;
    int lvl = (int)(tid & (NUM_LEVELS - 1));
    int pid = (int)(tid >> 4);
    if (pid >= n_points) return;

    // positions: 16 consecutive lanes share one point -> L1 broadcast
    float px = __ldg(pos + 3 * pid + 0);
    float py = __ldg(pos + 3 * pid + 1);
    float pz = __ldg(pos + 3 * pid + 2);
    px = fminf(fmaxf(px, 0.0f), 1.0f);
    py = fminf(fmaxf(py, 0.0f), 1.0f);
    pz = fminf(fmaxf(pz, 0.0f), 1.0f);

    int res_i = rp.res[lvl];
    float res = (float)res_i;

    float sx = px * res, sy = py * res, sz = pz * res;
    float fx = floorf(sx), fy = floorf(sy), fz = floorf(sz);
    float tx = sx - fx, ty = sy - fy, tz = sz - fz;

    int r1 = res_i - 1;
    int cx = min(max((int)fx, 0), r1);
    int cy = min(max((int)fy, 0), r1);
    int cz = min(max((int)fz, 0), r1);

    // hash(cx+i, cy+j, cz+k) = (cx+i) + (cy+j)*P2 + (cz+k)*P3 (mod 2^32), & TMASK
    uint32_t h0 = (uint32_t)cx + (uint32_t)cy * P2 + (uint32_t)cz * P3;

    const float2* __restrict__ tl =
        (const float2*)tables + (size_t)lvl * TABLE_SIZE;

    // label f_{ijk}: i = x-offset, j = y-offset, k = z-offset
    float2 f000 = __ldg(&tl[(h0)                 & TMASK]);
    float2 f001 = __ldg(&tl[(h0 + P3)            & TMASK]);
    float2 f010 = __ldg(&tl[(h0 + P2)            & TMASK]);
    float2 f011 = __ldg(&tl[(h0 + P2 + P3)       & TMASK]);
    float2 f100 = __ldg(&tl[(h0 + 1u)            & TMASK]);
    float2 f101 = __ldg(&tl[(h0 + 1u + P3)       & TMASK]);
    float2 f110 = __ldg(&tl[(h0 + 1u + P2)       & TMASK]);
    float2 f111 = __ldg(&tl[(h0 + 1u + P2 + P3)  & TMASK]);

    // Reference blend (note its permuted weight/axis pairing — replicate exactly):
    // c00 = feats[0]*(1-tx)+feats[1]*tx ; feats order = i*4 + j*2 + k
    float wx0 = 1.0f - tx, wy0 = 1.0f - ty, wz0 = 1.0f - tz;

    float c00x = f000.x * wx0 + f001.x * tx;
    float c00y = f000.y * wx0 + f001.y * tx;
    float c01x = f010.x * wx0 + f011.x * tx;
    float c01y = f010.y * wx0 + f011.y * tx;
    float c10x = f100.x * wx0 + f101.x * tx;
    float c10y = f100.y * wx0 + f101.y * tx;
    float c11x = f110.x * wx0 + f111.x * tx;
    float c11y = f110.y * wx0 + f111.y * tx;

    float c0x = c00x * wy0 + c10x * ty;
    float c0y = c00y * wy0 + c10y * ty;
    float c1x = c01x * wy0 + c11x * ty;
    float c1y = c01y * wy0 + c11y * ty;

    float2 r;
    r.x = c0x * wz0 + c1x * tz;
    r.y = c0y * wz0 + c1y * tz;

    // warp writes 2 points x 32 floats = 256 contiguous bytes
    *(float2*)(out + (size_t)pid * (2 * NUM_LEVELS) + 2 * lvl) = r;
}

extern "C" void kernel_launch(void* const* d_in, const int* in_sizes, int n_in,
                              void* d_out, int out_size)
{
    const float* positions = (const float*)d_in[0];
    const float* tables    = (const float*)d_in[1];
    float* out             = (float*)d_out;

    int n_points = in_sizes[0] / 3;

    // Reproduce the reference's resolution computation bit-exactly using the
    // same libm double path numpy uses, including int() truncation.
    ResParams rp;
    {
        double b = exp(log(2048.0 / 16.0) / 15.0);
        for (int l = 0; l < NUM_LEVELS; l++) {
            rp.res[l] = (int)(16.0 * pow(b, (double)l));
        }
    }

    long long total = (long long)n_points * NUM_LEVELS;
    int block = 256;
    long long grid = (total + block - 1) / block;

    hash_encoder_kernel<<<(unsigned)grid, block>>>(positions, tables, out,
                                                   n_points, rp);
}

// round 4
// speedup vs baseline: 1.0025x; 1.0025x over previous
#include <cuda_runtime.h>
#include <cstdint>
#include <math.h>

#define NUM_LEVELS 16
#define TABLE_SIZE (1u << 20)
#define TMASK (TABLE_SIZE - 1u)
#define P2 2654435761u
#define P3 805459861u

struct ResParams {
    int res[NUM_LEVELS];
};

// Table gather: non-coherent load with L2 evict_last cache-hint policy so the
// table working set (~94MB of hot sectors) stays resident in the 126MB L2
// instead of being flushed by the output store stream.
__device__ __forceinline__ float2 ldg_table(const float2* p, uint64_t policy) {
    float2 v;
    asm("ld.global.nc.L2::cache_hint.v2.f32 {%0,%1}, [%2], %3;"
        : "=f"(v.x), "=f"(v.y) : "l"(p), "l"(policy));
    return v;
}

__global__ __launch_bounds__(256)
void hash_encoder_kernel(const float* __restrict__ pos,
                         const float* __restrict__ tables,
                         float* __restrict__ out,
                         int n_points,
                         ResParams rp)
{
    long long tid = (long long)blockIdx.x * blockDim.x + threadIdx.x;
    int lvl = (int)(tid & (NUM_LEVELS - 1));
    int pid = (int)(tid >> 4);
    if (pid >= n_points) return;

    uint64_t pol_keep;
    asm("createpolicy.fractional.L2::evict_last.b64 %0, 1.0;" : "=l"(pol_keep));

    // positions: 16 consecutive lanes share one point -> L1 broadcast
    float px = __ldg(pos + 3 * pid + 0);
    float py = __ldg(pos + 3 * pid + 1);
    float pz = __ldg(pos + 3 * pid + 2);
    px = fminf(fmaxf(px, 0.0f), 1.0f);
    py = fminf(fmaxf(py, 0.0f), 1.0f);
    pz = fminf(fmaxf(pz, 0.0f), 1.0f);

    int res_i = rp.res[lvl];
    float res = (float)res_i;

    float sx = px * res, sy = py * res, sz = pz * res;
    float fx = floorf(sx), fy = floorf(sy), fz = floorf(sz);
    float tx = sx - fx, ty = sy - fy, tz = sz - fz;

    int r1 = res_i - 1;
    int cx = min(max((int)fx, 0), r1);
    int cy = min(max((int)fy, 0), r1);
    int cz = min(max((int)fz, 0), r1);

    // hash(cx+i, cy+j, cz+k) = (cx+i) + (cy+j)*P2 + (cz+k)*P3 (mod 2^32), & TMASK
    uint32_t h0 = (uint32_t)cx + (uint32_t)cy * P2 + (uint32_t)cz * P3;

    const float2* __restrict__ tl =
        (const float2*)tables + (size_t)lvl * TABLE_SIZE;

    // label f_{ijk}: i = x-offset, j = y-offset, k = z-offset
    float2 f000 = ldg_table(&tl[(h0)                 & TMASK], pol_keep);
    float2 f001 = ldg_table(&tl[(h0 + P3)            & TMASK], pol_keep);
    float2 f010 = ldg_table(&tl[(h0 + P2)            & TMASK], pol_keep);
    float2 f011 = ldg_table(&tl[(h0 + P2 + P3)       & TMASK], pol_keep);
    float2 f100 = ldg_table(&tl[(h0 + 1u)            & TMASK], pol_keep);
    float2 f101 = ldg_table(&tl[(h0 + 1u + P3)       & TMASK], pol_keep);
    float2 f110 = ldg_table(&tl[(h0 + 1u + P2)       & TMASK], pol_keep);
    float2 f111 = ldg_table(&tl[(h0 + 1u + P2 + P3)  & TMASK], pol_keep);

    // Reference blend (permuted weight/axis pairing — replicate exactly):
    float wx0 = 1.0f - tx, wy0 = 1.0f - ty, wz0 = 1.0f - tz;

    float c00x = f000.x * wx0 + f001.x * tx;
    float c00y = f000.y * wx0 + f001.y * tx;
    float c01x = f010.x * wx0 + f011.x * tx;
    float c01y = f010.y * wx0 + f011.y * tx;
    float c10x = f100.x * wx0 + f101.x * tx;
    float c10y = f100.y * wx0 + f101.y * tx;
    float c11x = f110.x * wx0 + f111.x * tx;
    float c11y = f110.y * wx0 + f111.y * tx;

    float c0x = c00x * wy0 + c10x * ty;
    float c0y = c00y * wy0 + c10y * ty;
    float c1x = c01x * wy0 + c11x * ty;
    float c1y = c01y * wy0 + c11y * ty;

    float2 r;
    r.x = c0x * wz0 + c1x * tz;
    r.y = c0y * wz0 + c1y * tz;

    // warp writes 2 points x 32 floats = 256 contiguous bytes;
    // streaming store (evict-first) keeps the output out of L2's way.
    __stcs((float2*)(out + (size_t)pid * (2 * NUM_LEVELS) + 2 * lvl), r);
}

extern "C" void kernel_launch(void* const* d_in, const int* in_sizes, int n_in,
                              void* d_out, int out_size)
{
    const float* positions = (const float*)d_in[0];
    const float* tables    = (const float*)d_in[1];
    float* out             = (float*)d_out;

    int n_points = in_sizes[0] / 3;

    // Max L1 carveout (no smem used) so small-level tables stay L1-resident.
    static bool carveout_set = false;
    if (!carveout_set) {
        cudaFuncSetAttribute(hash_encoder_kernel,
                             cudaFuncAttributePreferredSharedMemoryCarveout, 0);
        carveout_set = true;
    }

    // Reproduce the reference's resolution computation bit-exactly using the
    // same libm double path numpy uses, including int() truncation.
    ResParams rp;
    {
        double b = exp(log(2048.0 / 16.0) / 15.0);
        for (int l = 0; l < NUM_LEVELS; l++) {
            rp.res[l] = (int)(16.0 * pow(b, (double)l));
        }
    }

    long long total = (long long)n_points * NUM_LEVELS;
    int block = 256;
    long long grid = (total + block - 1) / block;

    hash_encoder_kernel<<<(unsigned)grid, block>>>(positions, tables, out,
                                                   n_points, rp);
}

// round 6
// speedup vs baseline: 1.0871x; 1.0844x over previous
#include <cuda_runtime.h>
#include <cstdint>
#include <math.h>

#define NUM_LEVELS 16
#define TABLE_SIZE (1u << 20)
#define TMASK (TABLE_SIZE - 1u)
#define P2 2654435761u
#define P3 805459861u

struct ResParams {
    int res[NUM_LEVELS];
};

// Load the x-pair of corners (table indices hm and (hm+1)&TMASK) with one
// aligned float4 gather plus a predicated float2 fixup for the odd case.
// f0 = table[hm] (i=0 corner), f1 = table[(hm+1)&TMASK] (i=1 corner).
__device__ __forceinline__ void load_pair(const float2* __restrict__ tl,
                                          uint32_t hm,
                                          float2& f0, float2& f1)
{
    uint32_t base = hm & ~1u;                       // even, base+1 <= TMASK
    float4 v = __ldg((const float4*)(tl + base));   // entries base, base+1
    bool odd = (hm & 1u) != 0u;

    float2 fix;
    fix.x = v.z; fix.y = v.w;
    if (odd) {
        // true i=1 corner sits at (hm+1) & TMASK (handles 2^20 wrap exactly)
        fix = __ldg(tl + ((hm + 1u) & TMASK));
    }
    f0.x = odd ? v.z : v.x;
    f0.y = odd ? v.w : v.y;
    f1.x = odd ? fix.x : v.z;
    f1.y = odd ? fix.y : v.w;
}

__global__ __launch_bounds__(256)
void hash_encoder_kernel(const float* __restrict__ pos,
                         const float* __restrict__ tables,
                         float* __restrict__ out,
                         int n_points,
                         ResParams rp)
{
    long long tid = (long long)blockIdx.x * blockDim.x + threadIdx.x;
    int lvl = (int)(tid & (NUM_LEVELS - 1));
    int pid = (int)(tid >> 4);
    if (pid >= n_points) return;

    // positions: 16 consecutive lanes share one point -> L1 broadcast
    float px = __ldg(pos + 3 * pid + 0);
    float py = __ldg(pos + 3 * pid + 1);
    float pz = __ldg(pos + 3 * pid + 2);
    px = fminf(fmaxf(px, 0.0f), 1.0f);
    py = fminf(fmaxf(py, 0.0f), 1.0f);
    pz = fminf(fmaxf(pz, 0.0f), 1.0f);

    int res_i = rp.res[lvl];
    float res = (float)res_i;

    float sx = px * res, sy = py * res, sz = pz * res;
    float fx = floorf(sx), fy = floorf(sy), fz = floorf(sz);
    float tx = sx - fx, ty = sy - fy, tz = sz - fz;

    int r1 = res_i - 1;
    int cx = min(max((int)fx, 0), r1);
    int cy = min(max((int)fy, 0), r1);
    int cz = min(max((int)fz, 0), r1);

    // hash(cx+i, cy+j, cz+k) = (cx+i)*1 + (cy+j)*P2 + (cz+k)*P3 (mod 2^32) & TMASK
    uint32_t h0 = (uint32_t)cx + (uint32_t)cy * P2 + (uint32_t)cz * P3;

    const float2* __restrict__ tl =
        (const float2*)tables + (size_t)lvl * TABLE_SIZE;

    // f_{ijk}: i -> +1, j -> +P2, k -> +P3. Pairs merged along i (adjacent
    // table entries H, H+1 -> single float4).
    float2 f000, f100, f001, f101, f010, f110, f011, f111;
    load_pair(tl, (h0)           & TMASK, f000, f100);
    load_pair(tl, (h0 + P3)      & TMASK, f001, f101);
    load_pair(tl, (h0 + P2)      & TMASK, f010, f110);
    load_pair(tl, (h0 + P2 + P3) & TMASK, f011, f111);

    // Reference blend, bit-exact (permuted weight/axis pairing):
    // tx pairs k-neighbors, ty pairs i-neighbors, tz pairs j-neighbors.
    float wx0 = 1.0f - tx, wy0 = 1.0f - ty, wz0 = 1.0f - tz;

    float c00x = f000.x * wx0 + f001.x * tx;
    float c00y = f000.y * wx0 + f001.y * tx;
    float c01x = f010.x * wx0 + f011.x * tx;
    float c01y = f010.y * wx0 + f011.y * tx;
    float c10x = f100.x * wx0 + f101.x * tx;
    float c10y = f100.y * wx0 + f101.y * tx;
    float c11x = f110.x * wx0 + f111.x * tx;
    float c11y = f110.y * wx0 + f111.y * tx;

    float c0x = c00x * wy0 + c10x * ty;
    float c0y = c00y * wy0 + c10y * ty;
    float c1x = c01x * wy0 + c11x * ty;
    float c1y = c01y * wy0 + c11y * ty;

    float2 r;
    r.x = c0x * wz0 + c1x * tz;
    r.y = c0y * wz0 + c1y * tz;

    // warp writes 2 points x 32 floats = 256 contiguous bytes;
    // streaming store keeps the output stream from displacing table lines.
    __stcs((float2*)(out + (size_t)pid * (2 * NUM_LEVELS) + 2 * lvl), r);
}

extern "C" void kernel_launch(void* const* d_in, const int* in_sizes, int n_in,
                              void* d_out, int out_size)
{
    const float* positions = (const float*)d_in[0];
    const float* tables    = (const float*)d_in[1];
    float* out             = (float*)d_out;

    int n_points = in_sizes[0] / 3;

    // Max L1 carveout (no smem used).
    static bool carveout_set = false;
    if (!carveout_set) {
        cudaFuncSetAttribute(hash_encoder_kernel,
                             cudaFuncAttributePreferredSharedMemoryCarveout, 0);
        carveout_set = true;
    }

    // Reproduce the reference's resolution computation bit-exactly using the
    // same libm double path numpy uses, including int() truncation.
    ResParams rp;
    {
        double b = exp(log(2048.0 / 16.0) / 15.0);
        for (int l = 0; l < NUM_LEVELS; l++) {
            rp.res[l] = (int)(16.0 * pow(b, (double)l));
        }
    }

    long long total = (long long)n_points * NUM_LEVELS;
    int block = 256;
    long long grid = (total + block - 1) / block;

    hash_encoder_kernel<<<(unsigned)grid, block>>>(positions, tables, out,
                                                   n_points, rp);
}